// round 3
// baseline (speedup 1.0000x reference)
#include <cuda_runtime.h>
#include <cstdint>

// Problem constants
#define N_TASKS 8192
#define EDIM    64
#define CDIM    128        // B*D = 2*64, batches stacked along columns
#define BJ      64         // j-tile per block
#define TI      64         // i-chunk
#define THRESH  0.7f

typedef unsigned long long ull;

// -------- device scratch (allocation-free rule: __device__ globals) --------
__device__ float g_V[N_TASKS * EDIM];      // V = U @ W                (2 MB)
__device__ float g_eff[N_TASKS * CDIM];    // gated states, packed     (4 MB)
__device__ float g_diag[N_TASKS];          // sigmoid(v_j.u_j + b)

// -------- small helpers --------
__device__ __forceinline__ void fma_x2(ull &d, ull a, ull b) {
    asm("fma.rn.f32x2 %0, %1, %2, %3;" : "=l"(d) : "l"(a), "l"(b), "l"(d));
}
__device__ __forceinline__ ull pack2(float x, float y) {
    ull r; asm("mov.b64 %0, {%1, %2};" : "=l"(r) : "f"(x), "f"(y)); return r;
}
__device__ __forceinline__ float2 unpack2(ull v) {
    float2 r; asm("mov.b64 {%0, %1}, %2;" : "=f"(r.x), "=f"(r.y) : "l"(v)); return r;
}
__device__ __forceinline__ void cpasync16(void* s, const void* g) {
    uint32_t sa = (uint32_t)__cvta_generic_to_shared(s);
    asm volatile("cp.async.cg.shared.global [%0], [%1], 16;" :: "r"(sa), "l"(g));
}
__device__ __forceinline__ void cp_commit() { asm volatile("cp.async.commit_group;"); }
__device__ __forceinline__ void cp_wait0()  { asm volatile("cp.async.wait_group 0;" ::: "memory"); }

__device__ __forceinline__ float fast_sigmoid(float x) {
    // 1/(1+e^-x) via MUFU ex2 + fast div; |err| ~1e-7 rel, fine vs 1e-3 tol
    return __fdividef(1.0f, 1.0f + __expf(-x));
}

// ============================================================================
// prep1: V = U @ W   (V[i][f] = sum_e U[i][e] * W[e][f])
// ============================================================================
__global__ void __launch_bounds__(256) prep_v_kernel(const float* __restrict__ U,
                                                     const float* __restrict__ W) {
    __shared__ float sW[64 * 64];
    __shared__ float sUa[64 * 65];     // pad 65 to rotate banks across rows
    const int tid = threadIdx.x;
    const int r0 = blockIdx.x * 64;

    for (int i = tid; i < 4096; i += 256) sW[i] = W[i];
    for (int i = tid; i < 4096; i += 256) {
        int r = i >> 6, e = i & 63;
        sUa[r * 65 + e] = U[(r0 + r) * 64 + e];
    }
    __syncthreads();

    const int row = tid & 63;
    const int f0  = (tid >> 6) * 16;
    ull acc[8];
    #pragma unroll
    for (int k = 0; k < 8; k++) acc[k] = 0ull;

    #pragma unroll 4
    for (int e = 0; e < 64; e++) {
        float u = sUa[row * 65 + e];
        ull u2 = pack2(u, u);
        const ull* wr = (const ull*)&sW[e * 64 + f0];   // broadcast across warp
        #pragma unroll
        for (int k = 0; k < 8; k++) fma_x2(acc[k], u2, wr[k]);
    }
    float* vout = &g_V[(r0 + row) * 64 + f0];
    #pragma unroll
    for (int k = 0; k < 8; k++) {
        float2 v = unpack2(acc[k]);
        vout[2 * k]     = v.x;
        vout[2 * k + 1] = v.y;
    }
}

// ============================================================================
// prep2: eff[j][b*64+d] = state * relu(prof - thr);  diag[j] = sig(v_j.u_j + b)
// ============================================================================
__global__ void __launch_bounds__(256) prep_eff_kernel(const float* __restrict__ states,
                                                       const float* __restrict__ prof,
                                                       const float* __restrict__ U,
                                                       const float* __restrict__ bptr) {
    const int tid   = threadIdx.x;
    const int lane  = tid & 31;
    const int warp  = tid >> 5;                 // 0..7
    const int jbase = blockIdx.x * 16 + warp * 2;
    const float bias = __ldg(bptr);

    #pragma unroll
    for (int q = 0; q < 2; q++) {
        const int j = jbase + q;
        // dot(V[j], U[j]) with warp reduce
        float s = g_V[j * 64 + lane]      * U[j * 64 + lane]
                + g_V[j * 64 + 32 + lane] * U[j * 64 + 32 + lane];
        #pragma unroll
        for (int o = 16; o > 0; o >>= 1) s += __shfl_xor_sync(0xffffffffu, s, o);
        if (lane == 0) g_diag[j] = fast_sigmoid(s + bias);

        const int c4 = lane * 4;                // 0..124
        const int b  = c4 >> 6;
        const int d  = c4 & 63;
        float g = prof[b * N_TASKS + j] - THRESH;
        g = g > 0.0f ? g : 0.0f;
        const float4 st = *(const float4*)&states[(b * N_TASKS + j) * 64 + d];
        float4 e4;
        e4.x = st.x * g; e4.y = st.y * g; e4.z = st.z * g; e4.w = st.w * g;
        *(float4*)&g_eff[j * CDIM + c4] = e4;
    }
}

// ============================================================================
// main: per j-tile (64 j), stream all i chunks of 64:
//   S = V_chunk @ U_j^T  -> P = sigmoid(S+b) -> C += P^T @ Eff_chunk
// epilogue: out = state + C - diag[j]*eff[j]
// ============================================================================
__global__ void __launch_bounds__(256, 1) main_kernel(const float* __restrict__ states,
                                                      const float* __restrict__ U,
                                                      const float* __restrict__ bptr,
                                                      float* __restrict__ out) {
    extern __shared__ float smem[];
    float* sU  = smem;                 // [64][68]
    float* sV0 = sU  + 64 * 68;        // [64][68] x2 (double buffer)
    float* sV1 = sV0 + 64 * 68;
    float* sE0 = sV1 + 64 * 68;        // [64][132] x2
    float* sE1 = sE0 + 64 * 132;
    float* sP  = sE1 + 64 * 132;       // [64][68]

    const int tid = threadIdx.x;
    const int jb  = blockIdx.x * BJ;
    const float bias = __ldg(bptr);

    // load U tile for this block's j's (persistent)
    for (int idx = tid; idx < 64 * 16; idx += 256) {
        int r = idx >> 4, q = idx & 15;
        *(float4*)&sU[r * 68 + q * 4] = *(const float4*)&U[(jb + r) * 64 + q * 4];
    }

    // prefetch chunk 0
    for (int idx = tid; idx < 1024; idx += 256) {
        int r = idx >> 4, q = idx & 15;
        cpasync16(&sV0[r * 68 + q * 4], &g_V[r * 64 + q * 4]);
    }
    for (int idx = tid; idx < 2048; idx += 256) {
        int r = idx >> 5, q = idx & 31;
        cpasync16(&sE0[r * 132 + q * 4], &g_eff[r * 128 + q * 4]);
    }
    cp_commit();

    // stage-2 mapping: 4 j x 8 c per thread
    const int c0   = (tid & 15) * 8;
    const int j0s2 = (tid >> 4) * 4;
    // stage-1 mapping: 4 i x 4 j per thread
    const int i0s1 = (tid >> 4) * 4;
    const int j0s1 = (tid & 15) * 4;

    ull accC[4][4];
    #pragma unroll
    for (int a = 0; a < 4; a++)
        #pragma unroll
        for (int b = 0; b < 4; b++) accC[a][b] = 0ull;

    cp_wait0();
    __syncthreads();

    const int NCHUNK = N_TASKS / TI;   // 128
    for (int k = 0; k < NCHUNK; k++) {
        float* sV = (k & 1) ? sV1 : sV0;
        float* sE = (k & 1) ? sE1 : sE0;

        // prefetch next chunk into the other buffer
        if (k + 1 < NCHUNK) {
            float* nV = (k & 1) ? sV0 : sV1;
            float* nE = (k & 1) ? sE0 : sE1;
            const int i0n = (k + 1) * TI;
            for (int idx = tid; idx < 1024; idx += 256) {
                int r = idx >> 4, q = idx & 15;
                cpasync16(&nV[r * 68 + q * 4], &g_V[(i0n + r) * 64 + q * 4]);
            }
            for (int idx = tid; idx < 2048; idx += 256) {
                int r = idx >> 5, q = idx & 31;
                cpasync16(&nE[r * 132 + q * 4], &g_eff[(i0n + r) * 128 + q * 4]);
            }
            cp_commit();
        }

        // ---- stage 1: S(4i x 4j) dot over E=64, f32x2-paired over e ----
        {
            ull accS[4][4];
            #pragma unroll
            for (int a = 0; a < 4; a++)
                #pragma unroll
                for (int b = 0; b < 4; b++) accS[a][b] = 0ull;

            #pragma unroll 4
            for (int e = 0; e < 64; e += 4) {
                ull v[4][2], u[4][2];
                #pragma unroll
                for (int a = 0; a < 4; a++) {
                    const ull* pv = (const ull*)&sV[(i0s1 + a) * 68 + e];
                    v[a][0] = pv[0]; v[a][1] = pv[1];
                    const ull* pu = (const ull*)&sU[(j0s1 + a) * 68 + e];
                    u[a][0] = pu[0]; u[a][1] = pu[1];
                }
                #pragma unroll
                for (int a = 0; a < 4; a++)
                    #pragma unroll
                    for (int b = 0; b < 4; b++) {
                        fma_x2(accS[a][b], v[a][0], u[b][0]);
                        fma_x2(accS[a][b], v[a][1], u[b][1]);
                    }
            }
            // sigmoid + write P (prev stage2 finished at end-of-loop sync)
            #pragma unroll
            for (int a = 0; a < 4; a++) {
                float2 t0 = unpack2(accS[a][0]);
                float2 t1 = unpack2(accS[a][1]);
                float2 t2 = unpack2(accS[a][2]);
                float2 t3 = unpack2(accS[a][3]);
                float4 pv;
                pv.x = fast_sigmoid(t0.x + t0.y + bias);
                pv.y = fast_sigmoid(t1.x + t1.y + bias);
                pv.z = fast_sigmoid(t2.x + t2.y + bias);
                pv.w = fast_sigmoid(t3.x + t3.y + bias);
                *(float4*)&sP[(i0s1 + a) * 68 + j0s1] = pv;
            }
        }
        __syncthreads();

        // ---- stage 2: C(4j x 8c) += P^T @ Eff over 64 i ----
        #pragma unroll 2
        for (int ii = 0; ii < TI; ii++) {
            float4 p = *(const float4*)&sP[ii * 68 + j0s2];
            const ull* ep = (const ull*)&sE[ii * 132 + c0];
            ull e0 = ep[0], e1 = ep[1], e2 = ep[2], e3 = ep[3];
            ull p0 = pack2(p.x, p.x), p1 = pack2(p.y, p.y);
            ull p2 = pack2(p.z, p.z), p3 = pack2(p.w, p.w);
            fma_x2(accC[0][0], p0, e0); fma_x2(accC[0][1], p0, e1);
            fma_x2(accC[0][2], p0, e2); fma_x2(accC[0][3], p0, e3);
            fma_x2(accC[1][0], p1, e0); fma_x2(accC[1][1], p1, e1);
            fma_x2(accC[1][2], p1, e2); fma_x2(accC[1][3], p1, e3);
            fma_x2(accC[2][0], p2, e0); fma_x2(accC[2][1], p2, e1);
            fma_x2(accC[2][2], p2, e2); fma_x2(accC[2][3], p2, e3);
            fma_x2(accC[3][0], p3, e0); fma_x2(accC[3][1], p3, e1);
            fma_x2(accC[3][2], p3, e2); fma_x2(accC[3][3], p3, e3);
        }

        cp_wait0();      // next chunk's data landed
        __syncthreads(); // protects sP / sV / sE reuse
    }

    // ---- epilogue: out = state + acc - diag*eff ----
    #pragma unroll
    for (int a = 0; a < 4; a++) {
        const int j = jb + j0s2 + a;
        const float dg = g_diag[j];
        #pragma unroll
        for (int cp = 0; cp < 4; cp++) {
            const int c = c0 + cp * 2;
            const int b = c >> 6;
            const int d = c & 63;
            const int idx = (b * N_TASKS + j) * 64 + d;
            float2 acc = unpack2(accC[a][cp]);
            float2 st  = *(const float2*)&states[idx];
            float2 ef  = *(const float2*)&g_eff[j * CDIM + c];
            float2 o;
            o.x = st.x + acc.x - dg * ef.x;
            o.y = st.y + acc.y - dg * ef.y;
            *(float2*)&out[idx] = o;
        }
    }
}

// ============================================================================
extern "C" void kernel_launch(void* const* d_in, const int* in_sizes, int n_in,
                              void* d_out, int out_size) {
    const float* states = (const float*)d_in[0];  // [2,8192,64]
    const float* prof   = (const float*)d_in[1];  // [2,8192]
    const float* U      = (const float*)d_in[2];  // [8192,64]
    const float* W      = (const float*)d_in[3];  // [1,64,64]
    const float* bias   = (const float*)d_in[4];  // [1]
    float* out = (float*)d_out;

    prep_v_kernel<<<N_TASKS / 64, 256>>>(U, W);
    prep_eff_kernel<<<N_TASKS / 16, 256>>>(states, prof, U, bias);

    const int smem_bytes = (64*68 + 2*64*68 + 2*64*132 + 64*68) * 4;  // 137216
    cudaFuncSetAttribute(main_kernel, cudaFuncAttributeMaxDynamicSharedMemorySize, smem_bytes);
    main_kernel<<<N_TASKS / BJ, 256, smem_bytes>>>(states, U, bias, out);
}

// round 5
// speedup vs baseline: 2.0425x; 2.0425x over previous
#include <cuda_runtime.h>
#include <cstdint>

// Problem constants
#define N_TASKS 8192
#define EDIM    64
#define CDIM    128        // B*D = 2*64, batches stacked along columns
#define BJ      64         // j-tile per block
#define TI      64         // i-chunk
#define THRESH  0.7f

typedef unsigned long long ull;

// -------- device scratch (allocation-free rule: __device__ globals) --------
__device__ float g_V[N_TASKS * EDIM];      // V = U @ W                (2 MB)
__device__ float g_eff[N_TASKS * CDIM];    // gated states, packed     (4 MB)
__device__ float g_diag[N_TASKS];          // sigmoid(v_j.u_j + b)

// -------- small helpers --------
__device__ __forceinline__ void fma_x2(ull &d, ull a, ull b) {
    asm("fma.rn.f32x2 %0, %1, %2, %3;" : "=l"(d) : "l"(a), "l"(b), "l"(d));
}
__device__ __forceinline__ ull pack2(float x, float y) {
    ull r; asm("mov.b64 %0, {%1, %2};" : "=l"(r) : "f"(x), "f"(y)); return r;
}
__device__ __forceinline__ float2 unpack2(ull v) {
    float2 r; asm("mov.b64 {%0, %1}, %2;" : "=f"(r.x), "=f"(r.y) : "l"(v)); return r;
}
__device__ __forceinline__ void cpasync16(void* s, const void* g) {
    uint32_t sa = (uint32_t)__cvta_generic_to_shared(s);
    asm volatile("cp.async.cg.shared.global [%0], [%1], 16;" :: "r"(sa), "l"(g));
}
__device__ __forceinline__ void cp_commit() { asm volatile("cp.async.commit_group;"); }
__device__ __forceinline__ void cp_wait0()  { asm volatile("cp.async.wait_group 0;" ::: "memory"); }

__device__ __forceinline__ float fast_sigmoid(float x) {
    return __fdividef(1.0f, 1.0f + __expf(-x));
}

// ============================================================================
// prep1: V = U @ W   (V[i][f] = sum_e U[i][e] * W[e][f])
// ============================================================================
__global__ void __launch_bounds__(256) prep_v_kernel(const float* __restrict__ U,
                                                     const float* __restrict__ W) {
    __shared__ float sW[64 * 64];
    __shared__ float sUa[64 * 65];
    const int tid = threadIdx.x;
    const int r0 = blockIdx.x * 64;

    for (int i = tid; i < 4096; i += 256) sW[i] = W[i];
    for (int i = tid; i < 4096; i += 256) {
        int r = i >> 6, e = i & 63;
        sUa[r * 65 + e] = U[(r0 + r) * 64 + e];
    }
    __syncthreads();

    const int row = tid & 63;
    const int f0  = (tid >> 6) * 16;
    ull acc[8];
    #pragma unroll
    for (int k = 0; k < 8; k++) acc[k] = 0ull;

    #pragma unroll 4
    for (int e = 0; e < 64; e++) {
        float u = sUa[row * 65 + e];
        ull u2 = pack2(u, u);
        const ull* wr = (const ull*)&sW[e * 64 + f0];
        #pragma unroll
        for (int k = 0; k < 8; k++) fma_x2(acc[k], u2, wr[k]);
    }
    float* vout = &g_V[(r0 + row) * 64 + f0];
    #pragma unroll
    for (int k = 0; k < 8; k++) {
        float2 v = unpack2(acc[k]);
        vout[2 * k]     = v.x;
        vout[2 * k + 1] = v.y;
    }
}

// ============================================================================
// prep2: eff[j][b*64+d] = state * relu(prof - thr);  diag[j] = sig(v_j.u_j + b)
// ============================================================================
__global__ void __launch_bounds__(256) prep_eff_kernel(const float* __restrict__ states,
                                                       const float* __restrict__ prof,
                                                       const float* __restrict__ U,
                                                       const float* __restrict__ bptr) {
    const int tid   = threadIdx.x;
    const int lane  = tid & 31;
    const int warp  = tid >> 5;
    const int jbase = blockIdx.x * 16 + warp * 2;
    const float bias = __ldg(bptr);

    #pragma unroll
    for (int q = 0; q < 2; q++) {
        const int j = jbase + q;
        float s = g_V[j * 64 + lane]      * U[j * 64 + lane]
                + g_V[j * 64 + 32 + lane] * U[j * 64 + 32 + lane];
        #pragma unroll
        for (int o = 16; o > 0; o >>= 1) s += __shfl_xor_sync(0xffffffffu, s, o);
        if (lane == 0) g_diag[j] = fast_sigmoid(s + bias);

        const int c4 = lane * 4;
        const int b  = c4 >> 6;
        const int d  = c4 & 63;
        float g = prof[b * N_TASKS + j] - THRESH;
        g = g > 0.0f ? g : 0.0f;
        const float4 st = *(const float4*)&states[(b * N_TASKS + j) * 64 + d];
        float4 e4;
        e4.x = st.x * g; e4.y = st.y * g; e4.z = st.z * g; e4.w = st.w * g;
        *(float4*)&g_eff[j * CDIM + c4] = e4;
    }
}

// ============================================================================
// main: per j-tile (64 j), stream all i chunks of 64:
//   S = V_chunk @ U_j^T  -> P = sigmoid(S+b) -> C += P^T @ Eff_chunk
// 512 threads, 2-D warp tiling, conflict-free smem layouts.
// ============================================================================
__global__ void __launch_bounds__(512, 1) main_kernel(const float* __restrict__ states,
                                                      const float* __restrict__ U,
                                                      const float* __restrict__ bptr,
                                                      float* __restrict__ out) {
    extern __shared__ float smem[];
    float* sUT = smem;                  // [64 e][68]  (U^T for this j-tile)
    float* sV0 = sUT + 64 * 68;         // [64 i][68]  x2 double buffer
    float* sV1 = sV0 + 64 * 68;
    float* sE0 = sV1 + 64 * 68;         // [64 i][132] x2
    float* sE1 = sE0 + 64 * 132;
    float* sP  = sE1 + 64 * 132;        // [64 i][68]  (j in columns)

    const int tid  = threadIdx.x;
    const int lane = tid & 31;
    const int w    = tid >> 5;          // 0..15
    const int jb   = blockIdx.x * BJ;
    const float bias = __ldg(bptr);

    // ---- build transposed U tile: sUT[e][j] = U[jb+j][e] ----
    for (int idx = tid; idx < 4096; idx += 512) {
        int j = idx >> 6, e = idx & 63;
        sUT[e * 68 + j] = U[(jb + j) * 64 + e];
    }

    // ---- prefetch chunk 0 ----
    for (int idx = tid; idx < 1024; idx += 512) {
        int r = idx >> 4, q = idx & 15;
        cpasync16(&sV0[r * 68 + q * 4], &g_V[r * 64 + q * 4]);
    }
    for (int idx = tid; idx < 2048; idx += 512) {
        int r = idx >> 5, q = idx & 31;
        cpasync16(&sE0[r * 132 + q * 4], &g_eff[r * 128 + q * 4]);
    }
    cp_commit();

    // ---- warp-tiled thread mappings ----
    // stage 1: warp tile = 16i x 16j ; thread = 2i x 4j
    const int j0s1 = (w & 3) * 16 + (lane & 3) * 4;
    const int i0s1 = (w >> 2) * 16 + (lane >> 2) * 2;
    // stage 2: warp tile = 16j x 32c ; thread = 2j x 8c
    const int c0   = (w & 3) * 32 + (lane & 3) * 8;
    const int j0s2 = (w >> 2) * 16 + (lane >> 2) * 2;

    ull accC[2][4];
    #pragma unroll
    for (int a = 0; a < 2; a++)
        #pragma unroll
        for (int b = 0; b < 4; b++) accC[a][b] = 0ull;

    cp_wait0();
    __syncthreads();

    const int NCHUNK = N_TASKS / TI;    // 128
    for (int k = 0; k < NCHUNK; k++) {
        float* sV = (k & 1) ? sV1 : sV0;
        float* sE = (k & 1) ? sE1 : sE0;

        // prefetch next chunk into the other buffer
        if (k + 1 < NCHUNK) {
            float* nV = (k & 1) ? sV0 : sV1;
            float* nE = (k & 1) ? sE0 : sE1;
            const int i0n = (k + 1) * TI;
            for (int idx = tid; idx < 1024; idx += 512) {
                int r = idx >> 4, q = idx & 15;
                cpasync16(&nV[r * 68 + q * 4], &g_V[(i0n + r) * 64 + q * 4]);
            }
            for (int idx = tid; idx < 2048; idx += 512) {
                int r = idx >> 5, q = idx & 31;
                cpasync16(&nE[r * 132 + q * 4], &g_eff[(i0n + r) * 128 + q * 4]);
            }
            cp_commit();
        }

        // ---- stage 1: S(2i x 4j), f32x2-paired over j ----
        {
            ull accS[2][2];
            accS[0][0] = accS[0][1] = accS[1][0] = accS[1][1] = 0ull;

            #pragma unroll 8
            for (int e = 0; e < 64; e += 4) {
                float4 va = *(const float4*)&sV[i0s1 * 68 + e];
                float4 vb = *(const float4*)&sV[(i0s1 + 1) * 68 + e];
                float4 u0 = *(const float4*)&sUT[(e + 0) * 68 + j0s1];
                float4 u1 = *(const float4*)&sUT[(e + 1) * 68 + j0s1];
                float4 u2 = *(const float4*)&sUT[(e + 2) * 68 + j0s1];
                float4 u3 = *(const float4*)&sUT[(e + 3) * 68 + j0s1];

                ull ua, ub, va2, vb2;
                ua = pack2(u0.x, u0.y); ub = pack2(u0.z, u0.w);
                va2 = pack2(va.x, va.x); vb2 = pack2(vb.x, vb.x);
                fma_x2(accS[0][0], va2, ua); fma_x2(accS[0][1], va2, ub);
                fma_x2(accS[1][0], vb2, ua); fma_x2(accS[1][1], vb2, ub);

                ua = pack2(u1.x, u1.y); ub = pack2(u1.z, u1.w);
                va2 = pack2(va.y, va.y); vb2 = pack2(vb.y, vb.y);
                fma_x2(accS[0][0], va2, ua); fma_x2(accS[0][1], va2, ub);
                fma_x2(accS[1][0], vb2, ua); fma_x2(accS[1][1], vb2, ub);

                ua = pack2(u2.x, u2.y); ub = pack2(u2.z, u2.w);
                va2 = pack2(va.z, va.z); vb2 = pack2(vb.z, vb.z);
                fma_x2(accS[0][0], va2, ua); fma_x2(accS[0][1], va2, ub);
                fma_x2(accS[1][0], vb2, ua); fma_x2(accS[1][1], vb2, ub);

                ua = pack2(u3.x, u3.y); ub = pack2(u3.z, u3.w);
                va2 = pack2(va.w, va.w); vb2 = pack2(vb.w, vb.w);
                fma_x2(accS[0][0], va2, ua); fma_x2(accS[0][1], va2, ub);
                fma_x2(accS[1][0], vb2, ua); fma_x2(accS[1][1], vb2, ub);
            }

            // sigmoid + write P rows (i0s1, i0s1+1), j-contiguous
            #pragma unroll
            for (int a = 0; a < 2; a++) {
                float2 t0 = unpack2(accS[a][0]);
                float2 t1 = unpack2(accS[a][1]);
                float4 pv;
                pv.x = fast_sigmoid(t0.x + bias);
                pv.y = fast_sigmoid(t0.y + bias);
                pv.z = fast_sigmoid(t1.x + bias);
                pv.w = fast_sigmoid(t1.y + bias);
                *(float4*)&sP[(i0s1 + a) * 68 + j0s1] = pv;
            }
        }
        __syncthreads();

        // ---- stage 2: C(2j x 8c) += P^T @ Eff over 64 i ----
        #pragma unroll 4
        for (int ii = 0; ii < TI; ii++) {
            ull p2 = *(const ull*)&sP[ii * 68 + j0s2];
            float2 pf = unpack2(p2);
            ulonglong2 ea = *(const ulonglong2*)&sE[ii * 132 + c0];
            ulonglong2 eb = *(const ulonglong2*)&sE[ii * 132 + c0 + 4];
            ull pa = pack2(pf.x, pf.x);
            ull pb = pack2(pf.y, pf.y);
            fma_x2(accC[0][0], pa, ea.x); fma_x2(accC[0][1], pa, ea.y);
            fma_x2(accC[0][2], pa, eb.x); fma_x2(accC[0][3], pa, eb.y);
            fma_x2(accC[1][0], pb, ea.x); fma_x2(accC[1][1], pb, ea.y);
            fma_x2(accC[1][2], pb, eb.x); fma_x2(accC[1][3], pb, eb.y);
        }

        cp_wait0();      // next chunk's data landed
        __syncthreads(); // protects sP / sV / sE reuse
    }

    // ---- epilogue: out = state + acc - diag*eff ----
    #pragma unroll
    for (int a = 0; a < 2; a++) {
        const int j  = jb + j0s2 + a;
        const float dg = g_diag[j];
        const int b  = c0 >> 6;
        const int d  = c0 & 63;
        const int idx = (b * N_TASKS + j) * 64 + d;

        float4 st_lo = *(const float4*)&states[idx];
        float4 st_hi = *(const float4*)&states[idx + 4];
        float4 ef_lo = *(const float4*)&g_eff[j * CDIM + c0];
        float4 ef_hi = *(const float4*)&g_eff[j * CDIM + c0 + 4];

        float2 a0 = unpack2(accC[a][0]);
        float2 a1 = unpack2(accC[a][1]);
        float2 a2 = unpack2(accC[a][2]);
        float2 a3 = unpack2(accC[a][3]);

        float4 o_lo, o_hi;
        o_lo.x = st_lo.x + a0.x - dg * ef_lo.x;
        o_lo.y = st_lo.y + a0.y - dg * ef_lo.y;
        o_lo.z = st_lo.z + a1.x - dg * ef_lo.z;
        o_lo.w = st_lo.w + a1.y - dg * ef_lo.w;
        o_hi.x = st_hi.x + a2.x - dg * ef_hi.x;
        o_hi.y = st_hi.y + a2.y - dg * ef_hi.y;
        o_hi.z = st_hi.z + a3.x - dg * ef_hi.z;
        o_hi.w = st_hi.w + a3.y - dg * ef_hi.w;

        *(float4*)&out[idx]     = o_lo;
        *(float4*)&out[idx + 4] = o_hi;
    }
}

// ============================================================================
extern "C" void kernel_launch(void* const* d_in, const int* in_sizes, int n_in,
                              void* d_out, int out_size) {
    const float* states = (const float*)d_in[0];  // [2,8192,64]
    const float* prof   = (const float*)d_in[1];  // [2,8192]
    const float* U      = (const float*)d_in[2];  // [8192,64]
    const float* W      = (const float*)d_in[3];  // [1,64,64]
    const float* bias   = (const float*)d_in[4];  // [1]
    float* out = (float*)d_out;

    prep_v_kernel<<<N_TASKS / 64, 256>>>(U, W);
    prep_eff_kernel<<<N_TASKS / 16, 256>>>(states, prof, U, bias);

    const int smem_bytes = (64*68 + 2*64*68 + 2*64*132 + 64*68) * 4;  // 137216
    cudaFuncSetAttribute(main_kernel, cudaFuncAttributeMaxDynamicSharedMemorySize, smem_bytes);
    main_kernel<<<N_TASKS / BJ, 512, smem_bytes>>>(states, U, bias, out);
}

// round 8
// speedup vs baseline: 6.3953x; 3.1312x over previous
#include <cuda_runtime.h>
#include <cuda_bf16.h>
#include <cstdint>

#define NT      8192
#define THRESH  0.7f
#define NCH     128         // i-chunks per CTA (full sweep)
#define TI      64
#define RS      72          // smem row stride in bf16 (144 B -> LDSM conflict-free)

typedef __nv_bfloat16 bf16;

// ---------------- device scratch (__device__ globals; no allocs) ----------------
__device__ float g_V[NT * 64];           // V = U @ W (fp32)
__device__ float g_eff[NT * 128];        // gated states fp32 [task][c], c=b*64+d
__device__ float g_diag[NT];             // sigmoid(u_j . v_j + b)
__device__ bf16  g_Uh[NT * 64], g_Ul[NT * 64];       // U hi/lo split
__device__ bf16  g_Vh[NT * 64], g_Vl[NT * 64];       // V hi/lo split
__device__ bf16  g_ETh[128 * NT], g_ETl[128 * NT];   // Eff^T [c][i] hi/lo

// ---------------- helpers ----------------
__device__ __forceinline__ uint32_t s2u(const void* p) {
    uint32_t a;
    asm("{ .reg .u64 t; cvta.to.shared.u64 t, %1; cvt.u32.u64 %0, t; }" : "=r"(a) : "l"(p));
    return a;
}
__device__ __forceinline__ void cpasync16(uint32_t dst, const void* src) {
    asm volatile("cp.async.cg.shared.global [%0], [%1], 16;" :: "r"(dst), "l"(src));
}
#define CP_COMMIT() asm volatile("cp.async.commit_group;")
#define CP_WAIT0()  asm volatile("cp.async.wait_group 0;" ::: "memory")

__device__ __forceinline__ void ldsm4(uint32_t* r, uint32_t addr) {
    asm volatile("ldmatrix.sync.aligned.m8n8.x4.shared.b16 {%0,%1,%2,%3}, [%4];"
        : "=r"(r[0]), "=r"(r[1]), "=r"(r[2]), "=r"(r[3]) : "r"(addr));
}
__device__ __forceinline__ void ldsm4t(uint32_t* r, uint32_t addr) {
    asm volatile("ldmatrix.sync.aligned.m8n8.x4.trans.shared.b16 {%0,%1,%2,%3}, [%4];"
        : "=r"(r[0]), "=r"(r[1]), "=r"(r[2]), "=r"(r[3]) : "r"(addr));
}
__device__ __forceinline__ void mma16816(float* c, const uint32_t* a, const uint32_t* b) {
    asm volatile("mma.sync.aligned.m16n8k16.row.col.f32.bf16.bf16.f32 "
        "{%0,%1,%2,%3}, {%4,%5,%6,%7}, {%8,%9}, {%0,%1,%2,%3};"
        : "+f"(c[0]), "+f"(c[1]), "+f"(c[2]), "+f"(c[3])
        : "r"(a[0]), "r"(a[1]), "r"(a[2]), "r"(a[3]), "r"(b[0]), "r"(b[1]));
}
__device__ __forceinline__ uint32_t bf16x2_of(float lo, float hi) {
    uint32_t r; asm("cvt.rn.bf16x2.f32 %0, %1, %2;" : "=r"(r) : "f"(hi), "f"(lo)); return r;
}
__device__ __forceinline__ float sigm(float x) {
    return __fdividef(1.0f, 1.0f + __expf(-x));
}

// ---------------- SMEM layout (bytes) ----------------
#define O_UH 0
#define O_UL 9216
#define O_V  18432                 // + buf*18432 + plane*9216      (2 bufs)
#define O_E  55296                 // + buf*36864 + plane*18432     (2 bufs)
#define O_P  129024                // + plane*9216
#define SMEM_TOTAL 147456

// ============================================================================
// prep_v: V = U@W fp32, plus hi/lo bf16 splits of V and U (32 rows/block)
// ============================================================================
__global__ void __launch_bounds__(256) prep_v_kernel(const float* __restrict__ U,
                                                     const float* __restrict__ W) {
    __shared__ float sW[64 * 64];
    __shared__ float sU[32 * 65];
    const int tid = threadIdx.x;
    const int r0 = blockIdx.x * 32;

    for (int i = tid; i < 4096; i += 256) sW[i] = W[i];
    for (int i = tid; i < 2048; i += 256) {
        int r = i >> 6, e = i & 63;
        sU[r * 65 + e] = U[(r0 + r) * 64 + e];
    }
    __syncthreads();

    const int r  = tid >> 3;
    const int f0 = (tid & 7) * 8;
    float acc[8];
    #pragma unroll
    for (int q = 0; q < 8; q++) acc[q] = 0.0f;

    #pragma unroll 8
    for (int e = 0; e < 64; e++) {
        float u = sU[r * 65 + e];
        float4 w0 = *(const float4*)&sW[e * 64 + f0];
        float4 w1 = *(const float4*)&sW[e * 64 + f0 + 4];
        acc[0] += u * w0.x; acc[1] += u * w0.y; acc[2] += u * w0.z; acc[3] += u * w0.w;
        acc[4] += u * w1.x; acc[5] += u * w1.y; acc[6] += u * w1.z; acc[7] += u * w1.w;
    }
    const int base = (r0 + r) * 64 + f0;
    #pragma unroll
    for (int q = 0; q < 8; q++) g_V[base + q] = acc[q];
    #pragma unroll
    for (int q = 0; q < 8; q += 2) {
        uint32_t h = bf16x2_of(acc[q], acc[q + 1]);
        float h0 = __uint_as_float(h << 16);
        float h1 = __uint_as_float(h & 0xFFFF0000u);
        uint32_t l = bf16x2_of(acc[q] - h0, acc[q + 1] - h1);
        *(uint32_t*)((bf16*)g_Vh + base + q) = h;
        *(uint32_t*)((bf16*)g_Vl + base + q) = l;
    }
    for (int i = tid; i < 1024; i += 256) {
        int rr = i >> 5, ep = (i & 31) * 2;
        float u0 = sU[rr * 65 + ep], u1 = sU[rr * 65 + ep + 1];
        uint32_t h = bf16x2_of(u0, u1);
        float h0 = __uint_as_float(h << 16);
        float h1 = __uint_as_float(h & 0xFFFF0000u);
        uint32_t l = bf16x2_of(u0 - h0, u1 - h1);
        int gi = (r0 + rr) * 64 + ep;
        *(uint32_t*)((bf16*)g_Uh + gi) = h;
        *(uint32_t*)((bf16*)g_Ul + gi) = l;
    }
}

// ============================================================================
// prep_et: g_eff fp32, Eff^T hi/lo planes, diag  (64 i-rows per block)
// ============================================================================
__global__ void __launch_bounds__(256) prep_et_kernel(const float* __restrict__ states,
                                                      const float* __restrict__ prof,
                                                      const float* __restrict__ U,
                                                      const float* __restrict__ bptr) {
    __shared__ float sT[128 * 64];   // [c][ii]
    const int tid = threadIdx.x;
    const int i0 = blockIdx.x * 64;
    const float bias = __ldg(bptr);

    for (int t = tid; t < 2048; t += 256) {
        int b = t >> 10, rem = t & 1023, ii = rem >> 4, d4 = rem & 15;
        int i = i0 + ii;
        float g = prof[b * NT + i] - THRESH;
        g = g > 0.0f ? g : 0.0f;
        float4 s4 = *(const float4*)&states[(b * NT + i) * 64 + d4 * 4];
        int c = b * 64 + d4 * 4;
        sT[(c + 0) * 64 + ii] = s4.x * g;
        sT[(c + 1) * 64 + ii] = s4.y * g;
        sT[(c + 2) * 64 + ii] = s4.z * g;
        sT[(c + 3) * 64 + ii] = s4.w * g;
        float4 e4; e4.x = s4.x * g; e4.y = s4.y * g; e4.z = s4.z * g; e4.w = s4.w * g;
        *(float4*)&g_eff[i * 128 + c] = e4;
    }
    const int w = tid >> 5, lane = tid & 31;
    #pragma unroll
    for (int q = 0; q < 8; q++) {
        int j = i0 + w * 8 + q;
        float s = g_V[j * 64 + lane] * U[j * 64 + lane]
                + g_V[j * 64 + 32 + lane] * U[j * 64 + 32 + lane];
        #pragma unroll
        for (int o = 16; o > 0; o >>= 1) s += __shfl_xor_sync(0xffffffffu, s, o);
        if (lane == 0) g_diag[j] = sigm(s + bias);
    }
    __syncthreads();
    for (int t = tid; t < 4096; t += 256) {
        int c = t >> 5, ii = (t & 31) * 2;
        float v0 = sT[c * 64 + ii], v1 = sT[c * 64 + ii + 1];
        uint32_t h = bf16x2_of(v0, v1);
        float h0 = __uint_as_float(h << 16);
        float h1 = __uint_as_float(h & 0xFFFF0000u);
        uint32_t l = bf16x2_of(v0 - h0, v1 - h1);
        *(uint32_t*)((bf16*)g_ETh + c * NT + i0 + ii) = h;
        *(uint32_t*)((bf16*)g_ETl + c * NT + i0 + ii) = l;
    }
}

// ============================================================================
// chunk prefetch: V (64x64 x2 planes) + ET (128x64 x2 planes), 144B rows
// ============================================================================
__device__ __forceinline__ void load_chunk(uint32_t sb, int k, int tid) {
    const int buf = k & 1;
    const int i0 = k * TI;
    const uint32_t vd = sb + O_V + buf * 18432;
    #pragma unroll
    for (int r = 0; r < 4; r++) {
        int id = r * 256 + tid;                      // 0..1023
        int pl = id >> 9, rem = id & 511, row = rem >> 3, q = rem & 7;
        const bf16* src = (pl ? g_Vl : g_Vh) + (i0 + row) * 64 + q * 8;
        cpasync16(vd + pl * 9216 + row * (RS * 2) + q * 16, src);
    }
    const uint32_t ed = sb + O_E + buf * 36864;
    #pragma unroll
    for (int r = 0; r < 8; r++) {
        int id = r * 256 + tid;                      // 0..2047
        int pl = id >> 10, rem = id & 1023, row = rem >> 3, q = rem & 7;
        const bf16* src = (pl ? g_ETl : g_ETh) + row * NT + i0 + q * 8;
        cpasync16(ed + pl * 18432 + row * (RS * 2) + q * 16, src);
    }
}

// ============================================================================
// main: 128 CTAs x 64-j tile; per chunk GEMM1 (mma) -> sigmoid -> GEMM2 (mma)
// ============================================================================
__global__ void __launch_bounds__(256, 1) main_kernel(const float* __restrict__ states,
                                                      const float* __restrict__ bptr,
                                                      float* __restrict__ out) {
    extern __shared__ char smem[];
    const uint32_t sb = s2u(smem);
    const int tid = threadIdx.x, w = tid >> 5, lane = tid & 31;
    const int jb = blockIdx.x * 64;
    const float bias = __ldg(bptr);

    // LDSM per-lane address components (m = lane>>3, r = lane&7)
    const int lm = lane >> 3, lr = lane & 7;
    const int aRow = lr + (lm & 1) * 8;   // A-style: row + (m&1)*8, col + (m>>1)*8
    const int aCol = (lm >> 1) * 8;
    const int bRow = lr + (lm >> 1) * 8;  // B-style: row + (m>>1)*8, col + (m&1)*8
    const int bCol = (lm & 1) * 8;

    // GEMM1 warp tile: 16i x 32j
    const int i0w = (w >> 1) * 16;
    const int jn0 = (w & 1) * 32;
    // GEMM2 warp tile: 16j x 64c
    const int j0w = (w >> 1) * 16;
    const int c0w = (w & 1) * 64;

    // ---- persistent U tile + chunk 0 ----
    #pragma unroll
    for (int r = 0; r < 4; r++) {
        int id = r * 256 + tid;
        int pl = id >> 9, rem = id & 511, row = rem >> 3, q = rem & 7;
        const bf16* src = (pl ? g_Ul : g_Uh) + (jb + row) * 64 + q * 8;
        cpasync16(sb + (pl ? O_UL : O_UH) + row * (RS * 2) + q * 16, src);
    }
    load_chunk(sb, 0, tid);
    CP_COMMIT();
    CP_WAIT0();
    __syncthreads();

    float cacc[8][4];
    #pragma unroll
    for (int q = 0; q < 8; q++)
        #pragma unroll
        for (int v = 0; v < 4; v++) cacc[q][v] = 0.0f;

    for (int k = 0; k < NCH; k++) {
        const int buf = k & 1;
        if (k + 1 < NCH) { load_chunk(sb, k + 1, tid); }
        CP_COMMIT();

        // ---- GEMM1: S[16i x 32j] = V . U^T  (3 passes: VhUh, VlUh, VhUl) ----
        float sacc[4][4];
        #pragma unroll
        for (int q = 0; q < 4; q++)
            #pragma unroll
            for (int v = 0; v < 4; v++) sacc[q][v] = 0.0f;

        #pragma unroll
        for (int p = 0; p < 3; p++) {
            const uint32_t vbase = sb + O_V + buf * 18432 + (p == 1 ? 9216 : 0);
            const uint32_t ubase = sb + (p == 2 ? O_UL : O_UH);
            #pragma unroll
            for (int kk = 0; kk < 4; kk++) {
                uint32_t a[4];
                ldsm4(a, vbase + ((i0w + aRow) * RS + kk * 16 + aCol) * 2);
                uint32_t b0[4], b1[4];
                ldsm4(b0, ubase + ((jn0 + bRow) * RS + kk * 16 + bCol) * 2);
                ldsm4(b1, ubase + ((jn0 + 16 + bRow) * RS + kk * 16 + bCol) * 2);
                mma16816(sacc[0], a, b0); mma16816(sacc[1], a, b0 + 2);
                mma16816(sacc[2], a, b1); mma16816(sacc[3], a, b1 + 2);
            }
        }

        // ---- sigmoid + hi/lo split -> P[i][j] in smem ----
        {
            const int pr = i0w + (lane >> 2);
            const int pc = jn0 + (lane & 3) * 2;
            #pragma unroll
            for (int nt = 0; nt < 4; nt++) {
                float s0 = sigm(sacc[nt][0] + bias);
                float s1 = sigm(sacc[nt][1] + bias);
                float s2 = sigm(sacc[nt][2] + bias);
                float s3 = sigm(sacc[nt][3] + bias);
                uint32_t h0 = bf16x2_of(s0, s1);
                uint32_t l0 = bf16x2_of(s0 - __uint_as_float(h0 << 16),
                                        s1 - __uint_as_float(h0 & 0xFFFF0000u));
                uint32_t h1 = bf16x2_of(s2, s3);
                uint32_t l1 = bf16x2_of(s2 - __uint_as_float(h1 << 16),
                                        s3 - __uint_as_float(h1 & 0xFFFF0000u));
                char* ph = smem + O_P +        (pr * RS + pc + nt * 8) * 2;
                char* pl = smem + O_P + 9216 + (pr * RS + pc + nt * 8) * 2;
                *(uint32_t*)ph = h0;
                *(uint32_t*)(ph + 8 * RS * 2) = h1;
                *(uint32_t*)pl = l0;
                *(uint32_t*)(pl + 8 * RS * 2) = l1;
            }
        }
        __syncthreads();

        // ---- GEMM2: C[16j x 64c] += P^T . ET  (3 passes: PhEh, PlEh, PhEl) ----
        #pragma unroll
        for (int p = 0; p < 3; p++) {
            const uint32_t pbase = sb + O_P + (p == 1 ? 9216 : 0);
            const uint32_t ebase = sb + O_E + buf * 36864 + (p == 2 ? 18432 : 0);
            #pragma unroll
            for (int kk = 0; kk < 4; kk++) {
                uint32_t a[4];   // P^T frag via ldmatrix.trans on P[i][j]
                ldsm4t(a, pbase + ((kk * 16 + bRow) * RS + j0w + bCol) * 2);
                #pragma unroll
                for (int ct = 0; ct < 4; ct++) {
                    uint32_t b[4];
                    ldsm4(b, ebase + ((c0w + ct * 16 + bRow) * RS + kk * 16 + bCol) * 2);
                    mma16816(cacc[ct * 2],     a, b);
                    mma16816(cacc[ct * 2 + 1], a, b + 2);
                }
            }
        }

        CP_WAIT0();
        __syncthreads();
    }

    // ---- epilogue: out = states + C - diag*eff ----
    {
        const int jrb = jb + j0w + (lane >> 2);
        const int ccb = (lane & 3) * 2;
        #pragma unroll
        for (int h = 0; h < 2; h++) {
            const int j = jrb + h * 8;
            const float dg = g_diag[j];
            #pragma unroll
            for (int q = 0; q < 8; q++) {
                const int c = c0w + (q >> 1) * 16 + (q & 1) * 8 + ccb;
                const int b = c >> 6, d = c & 63;
                const int idx = (b * NT + j) * 64 + d;
                float2 st = *(const float2*)&states[idx];
                float2 ef = *(const float2*)&g_eff[j * 128 + c];
                float2 o;
                o.x = st.x + cacc[q][h * 2]     - dg * ef.x;
                o.y = st.y + cacc[q][h * 2 + 1] - dg * ef.y;
                *(float2*)&out[idx] = o;
            }
        }
    }
}

// ============================================================================
extern "C" void kernel_launch(void* const* d_in, const int* in_sizes, int n_in,
                              void* d_out, int out_size) {
    const float* states = (const float*)d_in[0];  // [2,8192,64]
    const float* prof   = (const float*)d_in[1];  // [2,8192]
    const float* U      = (const float*)d_in[2];  // [8192,64]
    const float* W      = (const float*)d_in[3];  // [1,64,64]
    const float* bias   = (const float*)d_in[4];  // [1]
    float* out = (float*)d_out;

    prep_v_kernel<<<NT / 32, 256>>>(U, W);
    prep_et_kernel<<<NT / 64, 256>>>(states, prof, U, bias);

    cudaFuncSetAttribute(main_kernel, cudaFuncAttributeMaxDynamicSharedMemorySize, SMEM_TOTAL);
    main_kernel<<<NT / 64, 256, SMEM_TOTAL>>>(states, bias, out);
}

// round 10
// speedup vs baseline: 9.6540x; 1.5095x over previous
#include <cuda_runtime.h>
#include <cuda_bf16.h>
#include <cuda_fp16.h>
#include <cstdint>

#define NT      8192
#define THRESH  0.7f
#define NCH     128         // i-chunks per CTA (full sweep)
#define TI      64
#define RS      72          // smem row stride in 16-bit elems (144 B)

typedef __nv_bfloat16 bf16;

// ---------------- device scratch (__device__ globals; no allocs) ----------------
__device__ float  g_eff[NT * 128];        // gated states fp32 [task][c]
__device__ float  g_diag[NT];             // sigmoid(u_j . v_j + b)
__device__ bf16   g_Uh[NT * 64], g_Ul[NT * 64];   // U hi/lo split
__device__ bf16   g_Vh[NT * 64], g_Vl[NT * 64];   // V hi/lo split
__device__ __half g_ET[128 * NT];                 // Eff^T [c][i] fp16

// ---------------- helpers ----------------
__device__ __forceinline__ uint32_t s2u(const void* p) {
    uint32_t a;
    asm("{ .reg .u64 t; cvta.to.shared.u64 t, %1; cvt.u32.u64 %0, t; }" : "=r"(a) : "l"(p));
    return a;
}
__device__ __forceinline__ void cpasync16(uint32_t dst, const void* src) {
    asm volatile("cp.async.cg.shared.global [%0], [%1], 16;" :: "r"(dst), "l"(src));
}
#define CP_COMMIT() asm volatile("cp.async.commit_group;")
#define CP_WAIT0()  asm volatile("cp.async.wait_group 0;" ::: "memory")

__device__ __forceinline__ void ldsm4(uint32_t* r, uint32_t addr) {
    asm volatile("ldmatrix.sync.aligned.m8n8.x4.shared.b16 {%0,%1,%2,%3}, [%4];"
        : "=r"(r[0]), "=r"(r[1]), "=r"(r[2]), "=r"(r[3]) : "r"(addr));
}
__device__ __forceinline__ void ldsm4t(uint32_t* r, uint32_t addr) {
    asm volatile("ldmatrix.sync.aligned.m8n8.x4.trans.shared.b16 {%0,%1,%2,%3}, [%4];"
        : "=r"(r[0]), "=r"(r[1]), "=r"(r[2]), "=r"(r[3]) : "r"(addr));
}
__device__ __forceinline__ void mma_bf(float* c, const uint32_t* a, const uint32_t* b) {
    asm volatile("mma.sync.aligned.m16n8k16.row.col.f32.bf16.bf16.f32 "
        "{%0,%1,%2,%3}, {%4,%5,%6,%7}, {%8,%9}, {%0,%1,%2,%3};"
        : "+f"(c[0]), "+f"(c[1]), "+f"(c[2]), "+f"(c[3])
        : "r"(a[0]), "r"(a[1]), "r"(a[2]), "r"(a[3]), "r"(b[0]), "r"(b[1]));
}
__device__ __forceinline__ void mma_f16(float* c, const uint32_t* a, const uint32_t* b) {
    asm volatile("mma.sync.aligned.m16n8k16.row.col.f32.f16.f16.f32 "
        "{%0,%1,%2,%3}, {%4,%5,%6,%7}, {%8,%9}, {%0,%1,%2,%3};"
        : "+f"(c[0]), "+f"(c[1]), "+f"(c[2]), "+f"(c[3])
        : "r"(a[0]), "r"(a[1]), "r"(a[2]), "r"(a[3]), "r"(b[0]), "r"(b[1]));
}
__device__ __forceinline__ uint32_t bf16x2_of(float lo, float hi) {
    uint32_t r; asm("cvt.rn.bf16x2.f32 %0, %1, %2;" : "=r"(r) : "f"(hi), "f"(lo)); return r;
}
__device__ __forceinline__ uint32_t f16x2_of(float lo, float hi) {
    uint32_t r; asm("cvt.rn.f16x2.f32 %0, %1, %2;" : "=r"(r) : "f"(hi), "f"(lo)); return r;
}
__device__ __forceinline__ float sigm(float x) {
    return __fdividef(1.0f, 1.0f + __expf(-x));
}

// ---------------- SMEM layout (bytes) ----------------
#define O_UH 0
#define O_UL 9216
#define O_V  18432                 // + buf*18432 + plane*9216      (2 bufs)
#define O_E  55296                 // + buf*18432                   (2 bufs)
#define O_P  92160
#define SMEM_TOTAL 101376

// ============================================================================
// prep: per 64-row block — V=U@W, bf16 splits of U/V, diag, eff, ET(fp16)
// ============================================================================
#define PREP_SMEM ((4096 + 64*65 + 128*64) * 4)
__global__ void __launch_bounds__(256) prep_kernel(const float* __restrict__ states,
                                                   const float* __restrict__ prof,
                                                   const float* __restrict__ U,
                                                   const float* __restrict__ W,
                                                   const float* __restrict__ bptr) {
    extern __shared__ float sm[];
    float* sW = sm;                    // [64][64]
    float* sU = sm + 4096;             // [64][65]
    float* sT = sm + 4096 + 64 * 65;   // [128 c][64 ii]
    const int tid = threadIdx.x;
    const int r0 = blockIdx.x * 64;
    const float bias = __ldg(bptr);

    for (int i = tid; i < 4096; i += 256) sW[i] = W[i];
    for (int i = tid; i < 4096; i += 256) {
        int r = i >> 6, e = i & 63;
        sU[r * 65 + e] = U[(r0 + r) * 64 + e];
    }
    // eff + sT (transpose), independent of W/U
    for (int t = tid; t < 2048; t += 256) {
        int b = t >> 10, rem = t & 1023, ii = rem >> 4, d4 = rem & 15;
        int i = r0 + ii;
        float g = prof[b * NT + i] - THRESH;
        g = g > 0.0f ? g : 0.0f;
        float4 s4 = *(const float4*)&states[(b * NT + i) * 64 + d4 * 4];
        int c = b * 64 + d4 * 4;
        sT[(c + 0) * 64 + ii] = s4.x * g;
        sT[(c + 1) * 64 + ii] = s4.y * g;
        sT[(c + 2) * 64 + ii] = s4.z * g;
        sT[(c + 3) * 64 + ii] = s4.w * g;
        float4 e4; e4.x = s4.x * g; e4.y = s4.y * g; e4.z = s4.z * g; e4.w = s4.w * g;
        *(float4*)&g_eff[i * 128 + c] = e4;
    }
    __syncthreads();

    // V rows: thread -> row = tid>>2 (64 rows), f0 = (tid&3)*16
    const int row = tid >> 2, f0 = (tid & 3) * 16;
    float acc[16];
    #pragma unroll
    for (int q = 0; q < 16; q++) acc[q] = 0.0f;
    #pragma unroll 8
    for (int e = 0; e < 64; e++) {
        float u = sU[row * 65 + e];
        #pragma unroll
        for (int q4 = 0; q4 < 4; q4++) {
            float4 wv = *(const float4*)&sW[e * 64 + f0 + q4 * 4];
            acc[q4 * 4 + 0] += u * wv.x; acc[q4 * 4 + 1] += u * wv.y;
            acc[q4 * 4 + 2] += u * wv.z; acc[q4 * 4 + 3] += u * wv.w;
        }
    }
    const int base = (r0 + row) * 64 + f0;
    #pragma unroll
    for (int q = 0; q < 16; q += 2) {
        uint32_t h = bf16x2_of(acc[q], acc[q + 1]);
        float h0 = __uint_as_float(h << 16);
        float h1 = __uint_as_float(h & 0xFFFF0000u);
        uint32_t l = bf16x2_of(acc[q] - h0, acc[q + 1] - h1);
        *(uint32_t*)((bf16*)g_Vh + base + q) = h;
        *(uint32_t*)((bf16*)g_Vl + base + q) = l;
    }
    // diag: quad-reduce u.v
    float s = 0.0f;
    #pragma unroll
    for (int q = 0; q < 16; q++) s += acc[q] * sU[row * 65 + f0 + q];
    s += __shfl_xor_sync(0xffffffffu, s, 1);
    s += __shfl_xor_sync(0xffffffffu, s, 2);
    if ((tid & 3) == 0) g_diag[r0 + row] = sigm(s + bias);

    // U splits
    for (int i = tid; i < 2048; i += 256) {
        int rr = i >> 5, ep = (i & 31) * 2;
        float u0 = sU[rr * 65 + ep], u1 = sU[rr * 65 + ep + 1];
        uint32_t h = bf16x2_of(u0, u1);
        float h0 = __uint_as_float(h << 16);
        float h1 = __uint_as_float(h & 0xFFFF0000u);
        uint32_t l = bf16x2_of(u0 - h0, u1 - h1);
        int gi = (r0 + rr) * 64 + ep;
        *(uint32_t*)((bf16*)g_Uh + gi) = h;
        *(uint32_t*)((bf16*)g_Ul + gi) = l;
    }
    // ET fp16 (sT complete since pre-sync)
    for (int t = tid; t < 4096; t += 256) {
        int c = t >> 5, ii = (t & 31) * 2;
        __half2 h2 = __floats2half2_rn(sT[c * 64 + ii], sT[c * 64 + ii + 1]);
        *(__half2*)((__half*)g_ET + (size_t)c * NT + r0 + ii) = h2;
    }
}

// ============================================================================
// chunk prefetch: V (64x64, 2 bf16 planes) + ET (128x64 fp16), 144B rows
// ============================================================================
__device__ __forceinline__ void load_chunk(uint32_t sb, int k, int tid) {
    const int buf = k & 1;
    const int i0 = k * TI;
    const uint32_t vd = sb + O_V + buf * 18432;
    #pragma unroll
    for (int r = 0; r < 4; r++) {
        int id = r * 256 + tid;                      // 0..1023
        int pl = id >> 9, rem = id & 511, row = rem >> 3, q = rem & 7;
        const bf16* src = (pl ? g_Vl : g_Vh) + (i0 + row) * 64 + q * 8;
        cpasync16(vd + pl * 9216 + row * (RS * 2) + q * 16, src);
    }
    const uint32_t ed = sb + O_E + buf * 18432;
    #pragma unroll
    for (int r = 0; r < 4; r++) {
        int id = r * 256 + tid;                      // 0..1023
        int row = id >> 3, q = id & 7;
        const __half* src = g_ET + (size_t)row * NT + i0 + q * 8;
        cpasync16(ed + row * (RS * 2) + q * 16, src);
    }
}

// ============================================================================
// main: 128 CTAs x 64-j tile; GEMM1 bf16 3-pass -> sigmoid -> GEMM2 fp16 1-pass
// ============================================================================
__global__ void __launch_bounds__(256, 1) main_kernel(const float* __restrict__ states,
                                                      const float* __restrict__ bptr,
                                                      float* __restrict__ out) {
    extern __shared__ char smem[];
    const uint32_t sb = s2u(smem);
    const int tid = threadIdx.x, w = tid >> 5, lane = tid & 31;
    const int jb = blockIdx.x * 64;
    const float bias = __ldg(bptr);

    const int lm = lane >> 3, lr = lane & 7;
    const int aRow = lr + (lm & 1) * 8;
    const int aCol = (lm >> 1) * 8;
    const int bRow = lr + (lm >> 1) * 8;
    const int bCol = (lm & 1) * 8;

    const int i0w = (w >> 1) * 16;     // GEMM1: 16i x 32j per warp
    const int jn0 = (w & 1) * 32;
    const int j0w = (w >> 1) * 16;     // GEMM2: 16j x 64c per warp
    const int c0w = (w & 1) * 64;

    // ---- persistent U tile + chunk 0 ----
    #pragma unroll
    for (int r = 0; r < 4; r++) {
        int id = r * 256 + tid;
        int pl = id >> 9, rem = id & 511, row = rem >> 3, q = rem & 7;
        const bf16* src = (pl ? g_Ul : g_Uh) + (jb + row) * 64 + q * 8;
        cpasync16(sb + (pl ? O_UL : O_UH) + row * (RS * 2) + q * 16, src);
    }
    load_chunk(sb, 0, tid);
    CP_COMMIT();
    CP_WAIT0();
    __syncthreads();

    // ---- hoist U fragments (persistent in registers) ----
    uint32_t UhF[4][8], UlF[4][8];
    #pragma unroll
    for (int kk = 0; kk < 4; kk++) {
        ldsm4(&UhF[kk][0], sb + O_UH + ((jn0 + bRow) * RS + kk * 16 + bCol) * 2);
        ldsm4(&UhF[kk][4], sb + O_UH + ((jn0 + 16 + bRow) * RS + kk * 16 + bCol) * 2);
        ldsm4(&UlF[kk][0], sb + O_UL + ((jn0 + bRow) * RS + kk * 16 + bCol) * 2);
        ldsm4(&UlF[kk][4], sb + O_UL + ((jn0 + 16 + bRow) * RS + kk * 16 + bCol) * 2);
    }

    float cacc[8][4];
    #pragma unroll
    for (int q = 0; q < 8; q++)
        #pragma unroll
        for (int v = 0; v < 4; v++) cacc[q][v] = 0.0f;

    for (int k = 0; k < NCH; k++) {
        const int buf = k & 1;
        if (k + 1 < NCH) load_chunk(sb, k + 1, tid);
        CP_COMMIT();

        // ---- GEMM1: S[16i x 32j] = V . U^T  (VhUh, VlUh, VhUl) ----
        const uint32_t vbase = sb + O_V + buf * 18432;
        uint32_t VhF[4][4], VlF[4][4];
        #pragma unroll
        for (int kk = 0; kk < 4; kk++)
            ldsm4(VhF[kk], vbase + ((i0w + aRow) * RS + kk * 16 + aCol) * 2);
        #pragma unroll
        for (int kk = 0; kk < 4; kk++)
            ldsm4(VlF[kk], vbase + 9216 + ((i0w + aRow) * RS + kk * 16 + aCol) * 2);

        float sacc[4][4];
        #pragma unroll
        for (int q = 0; q < 4; q++)
            #pragma unroll
            for (int v = 0; v < 4; v++) sacc[q][v] = 0.0f;

        #pragma unroll
        for (int kk = 0; kk < 4; kk++) {
            mma_bf(sacc[0], VhF[kk], &UhF[kk][0]); mma_bf(sacc[1], VhF[kk], &UhF[kk][2]);
            mma_bf(sacc[2], VhF[kk], &UhF[kk][4]); mma_bf(sacc[3], VhF[kk], &UhF[kk][6]);
        }
        #pragma unroll
        for (int kk = 0; kk < 4; kk++) {
            mma_bf(sacc[0], VlF[kk], &UhF[kk][0]); mma_bf(sacc[1], VlF[kk], &UhF[kk][2]);
            mma_bf(sacc[2], VlF[kk], &UhF[kk][4]); mma_bf(sacc[3], VlF[kk], &UhF[kk][6]);
        }
        #pragma unroll
        for (int kk = 0; kk < 4; kk++) {
            mma_bf(sacc[0], VhF[kk], &UlF[kk][0]); mma_bf(sacc[1], VhF[kk], &UlF[kk][2]);
            mma_bf(sacc[2], VhF[kk], &UlF[kk][4]); mma_bf(sacc[3], VhF[kk], &UlF[kk][6]);
        }

        // ---- sigmoid -> P fp16 ----
        {
            const int pr = i0w + (lane >> 2);
            const int pc = jn0 + (lane & 3) * 2;
            #pragma unroll
            for (int nt = 0; nt < 4; nt++) {
                float s0 = sigm(sacc[nt][0] + bias);
                float s1 = sigm(sacc[nt][1] + bias);
                float s2 = sigm(sacc[nt][2] + bias);
                float s3 = sigm(sacc[nt][3] + bias);
                uint32_t h0 = f16x2_of(s0, s1);
                uint32_t h1 = f16x2_of(s2, s3);
                char* ph = smem + O_P + (pr * RS + pc + nt * 8) * 2;
                *(uint32_t*)ph = h0;
                *(uint32_t*)(ph + 8 * RS * 2) = h1;
            }
        }
        __syncthreads();

        // ---- GEMM2: C[16j x 64c] += P^T . ET  (fp16 single pass) ----
        {
            const uint32_t ebase = sb + O_E + buf * 18432;
            #pragma unroll
            for (int kk = 0; kk < 4; kk++) {
                uint32_t a[4];
                ldsm4t(a, sb + O_P + ((kk * 16 + bRow) * RS + j0w + bCol) * 2);
                #pragma unroll
                for (int ct = 0; ct < 4; ct++) {
                    uint32_t b[4];
                    ldsm4(b, ebase + ((c0w + ct * 16 + bRow) * RS + kk * 16 + bCol) * 2);
                    mma_f16(cacc[ct * 2],     a, b);
                    mma_f16(cacc[ct * 2 + 1], a, b + 2);
                }
            }
        }

        CP_WAIT0();
        __syncthreads();
    }

    // ---- epilogue: out = states + C - diag*eff ----
    {
        const int jrb = jb + j0w + (lane >> 2);
        const int ccb = (lane & 3) * 2;
        #pragma unroll
        for (int h = 0; h < 2; h++) {
            const int j = jrb + h * 8;
            const float dg = g_diag[j];
            #pragma unroll
            for (int q = 0; q < 8; q++) {
                const int c = c0w + (q >> 1) * 16 + (q & 1) * 8 + ccb;
                const int b = c >> 6, d = c & 63;
                const int idx = (b * NT + j) * 64 + d;
                float2 st = *(const float2*)&states[idx];
                float2 ef = *(const float2*)&g_eff[j * 128 + c];
                float2 o;
                o.x = st.x + cacc[q][h * 2]     - dg * ef.x;
                o.y = st.y + cacc[q][h * 2 + 1] - dg * ef.y;
                *(float2*)&out[idx] = o;
            }
        }
    }
}

// ============================================================================
extern "C" void kernel_launch(void* const* d_in, const int* in_sizes, int n_in,
                              void* d_out, int out_size) {
    const float* states = (const float*)d_in[0];  // [2,8192,64]
    const float* prof   = (const float*)d_in[1];  // [2,8192]
    const float* U      = (const float*)d_in[2];  // [8192,64]
    const float* W      = (const float*)d_in[3];  // [1,64,64]
    const float* bias   = (const float*)d_in[4];  // [1]
    float* out = (float*)d_out;

    cudaFuncSetAttribute(prep_kernel, cudaFuncAttributeMaxDynamicSharedMemorySize, PREP_SMEM);
    prep_kernel<<<NT / 64, 256, PREP_SMEM>>>(states, prof, U, W, bias);

    cudaFuncSetAttribute(main_kernel, cudaFuncAttributeMaxDynamicSharedMemorySize, SMEM_TOTAL);
    main_kernel<<<NT / 64, 256, SMEM_TOTAL>>>(states, bias, out);
}

// round 12
// speedup vs baseline: 10.0853x; 1.0447x over previous
#include <cuda_runtime.h>
#include <cuda_bf16.h>
#include <cuda_fp16.h>
#include <cstdint>

#define NT      8192
#define THRESH  0.7f
#define NCH     64          // i-chunks per CTA
#define TI      128         // i per chunk
#define RS      72          // V/U/P smem row stride in 16-bit elems (144 B)
#define RSE     136         // E smem row stride in 16-bit elems (272 B)

typedef __nv_bfloat16 bf16;

// ---------------- device scratch (__device__ globals; no allocs) ----------------
__device__ float  g_eff[NT * 128];        // gated states fp32 [task][c]
__device__ float  g_diag[NT];             // sigmoid(u_j . v_j + b)
__device__ bf16   g_Uh[NT * 64], g_Ul[NT * 64];   // U hi/lo split
__device__ bf16   g_Vh[NT * 64], g_Vl[NT * 64];   // V hi/lo split
__device__ __half g_ET[128 * NT];                 // Eff^T [c][i] fp16

// ---------------- helpers ----------------
__device__ __forceinline__ uint32_t s2u(const void* p) {
    uint32_t a;
    asm("{ .reg .u64 t; cvta.to.shared.u64 t, %1; cvt.u32.u64 %0, t; }" : "=r"(a) : "l"(p));
    return a;
}
__device__ __forceinline__ void cpasync16(uint32_t dst, const void* src) {
    asm volatile("cp.async.cg.shared.global [%0], [%1], 16;" :: "r"(dst), "l"(src));
}
#define CP_COMMIT() asm volatile("cp.async.commit_group;")
#define CP_WAIT0()  asm volatile("cp.async.wait_group 0;" ::: "memory")

__device__ __forceinline__ void ldsm4(uint32_t* r, uint32_t addr) {
    asm volatile("ldmatrix.sync.aligned.m8n8.x4.shared.b16 {%0,%1,%2,%3}, [%4];"
        : "=r"(r[0]), "=r"(r[1]), "=r"(r[2]), "=r"(r[3]) : "r"(addr));
}
__device__ __forceinline__ void ldsm4t(uint32_t* r, uint32_t addr) {
    asm volatile("ldmatrix.sync.aligned.m8n8.x4.trans.shared.b16 {%0,%1,%2,%3}, [%4];"
        : "=r"(r[0]), "=r"(r[1]), "=r"(r[2]), "=r"(r[3]) : "r"(addr));
}
__device__ __forceinline__ void mma_bf(float* c, const uint32_t* a, const uint32_t* b) {
    asm volatile("mma.sync.aligned.m16n8k16.row.col.f32.bf16.bf16.f32 "
        "{%0,%1,%2,%3}, {%4,%5,%6,%7}, {%8,%9}, {%0,%1,%2,%3};"
        : "+f"(c[0]), "+f"(c[1]), "+f"(c[2]), "+f"(c[3])
        : "r"(a[0]), "r"(a[1]), "r"(a[2]), "r"(a[3]), "r"(b[0]), "r"(b[1]));
}
__device__ __forceinline__ void mma_f16(float* c, const uint32_t* a, const uint32_t* b) {
    asm volatile("mma.sync.aligned.m16n8k16.row.col.f32.f16.f16.f32 "
        "{%0,%1,%2,%3}, {%4,%5,%6,%7}, {%8,%9}, {%0,%1,%2,%3};"
        : "+f"(c[0]), "+f"(c[1]), "+f"(c[2]), "+f"(c[3])
        : "r"(a[0]), "r"(a[1]), "r"(a[2]), "r"(a[3]), "r"(b[0]), "r"(b[1]));
}
__device__ __forceinline__ uint32_t bf16x2_of(float lo, float hi) {
    uint32_t r; asm("cvt.rn.bf16x2.f32 %0, %1, %2;" : "=r"(r) : "f"(hi), "f"(lo)); return r;
}
__device__ __forceinline__ uint32_t f16x2_of(float lo, float hi) {
    uint32_t r; asm("cvt.rn.f16x2.f32 %0, %1, %2;" : "=r"(r) : "f"(hi), "f"(lo)); return r;
}
// sigmoid(x) = 0.5 + 0.5*tanh(x/2)  — single HW MUFU op
__device__ __forceinline__ float sigm(float x) {
    float t; asm("tanh.approx.f32 %0, %1;" : "=f"(t) : "f"(0.5f * x));
    return fmaf(0.5f, t, 0.5f);
}

// ---------------- SMEM layout (bytes) ----------------
#define O_UH 0                    // 64 x 144
#define O_UL 9216
#define O_V  18432                // + buf*36864 + plane*18432   (2 bufs, 128 rows x 144B)
#define O_E  92160                // + buf*34816                 (2 bufs, 128 rows x 272B)
#define O_P  161792               // 128 rows x 144B
#define SMEM_TOTAL 180224

// ============================================================================
// prep: per 64-row block — V=U@W, bf16 splits of U/V, diag, eff, ET(fp16)
// ============================================================================
#define PREP_SMEM ((4096 + 64*65 + 128*64) * 4)
__global__ void __launch_bounds__(256) prep_kernel(const float* __restrict__ states,
                                                   const float* __restrict__ prof,
                                                   const float* __restrict__ U,
                                                   const float* __restrict__ W,
                                                   const float* __restrict__ bptr) {
    extern __shared__ float sm[];
    float* sW = sm;                    // [64][64]
    float* sU = sm + 4096;             // [64][65]
    float* sT = sm + 4096 + 64 * 65;   // [128 c][64 ii]
    const int tid = threadIdx.x;
    const int r0 = blockIdx.x * 64;
    const float bias = __ldg(bptr);

    for (int i = tid; i < 4096; i += 256) sW[i] = W[i];
    for (int i = tid; i < 4096; i += 256) {
        int r = i >> 6, e = i & 63;
        sU[r * 65 + e] = U[(r0 + r) * 64 + e];
    }
    for (int t = tid; t < 2048; t += 256) {
        int b = t >> 10, rem = t & 1023, ii = rem >> 4, d4 = rem & 15;
        int i = r0 + ii;
        float g = prof[b * NT + i] - THRESH;
        g = g > 0.0f ? g : 0.0f;
        float4 s4 = *(const float4*)&states[(b * NT + i) * 64 + d4 * 4];
        int c = b * 64 + d4 * 4;
        sT[(c + 0) * 64 + ii] = s4.x * g;
        sT[(c + 1) * 64 + ii] = s4.y * g;
        sT[(c + 2) * 64 + ii] = s4.z * g;
        sT[(c + 3) * 64 + ii] = s4.w * g;
        float4 e4; e4.x = s4.x * g; e4.y = s4.y * g; e4.z = s4.z * g; e4.w = s4.w * g;
        *(float4*)&g_eff[i * 128 + c] = e4;
    }
    __syncthreads();

    const int row = tid >> 2, f0 = (tid & 3) * 16;
    float acc[16];
    #pragma unroll
    for (int q = 0; q < 16; q++) acc[q] = 0.0f;
    #pragma unroll 8
    for (int e = 0; e < 64; e++) {
        float u = sU[row * 65 + e];
        #pragma unroll
        for (int q4 = 0; q4 < 4; q4++) {
            float4 wv = *(const float4*)&sW[e * 64 + f0 + q4 * 4];
            acc[q4 * 4 + 0] += u * wv.x; acc[q4 * 4 + 1] += u * wv.y;
            acc[q4 * 4 + 2] += u * wv.z; acc[q4 * 4 + 3] += u * wv.w;
        }
    }
    const int base = (r0 + row) * 64 + f0;
    #pragma unroll
    for (int q = 0; q < 16; q += 2) {
        uint32_t h = bf16x2_of(acc[q], acc[q + 1]);
        float h0 = __uint_as_float(h << 16);
        float h1 = __uint_as_float(h & 0xFFFF0000u);
        uint32_t l = bf16x2_of(acc[q] - h0, acc[q + 1] - h1);
        *(uint32_t*)((bf16*)g_Vh + base + q) = h;
        *(uint32_t*)((bf16*)g_Vl + base + q) = l;
    }
    float s = 0.0f;
    #pragma unroll
    for (int q = 0; q < 16; q++) s += acc[q] * sU[row * 65 + f0 + q];
    s += __shfl_xor_sync(0xffffffffu, s, 1);
    s += __shfl_xor_sync(0xffffffffu, s, 2);
    if ((tid & 3) == 0) g_diag[r0 + row] = sigm(s + bias);

    for (int i = tid; i < 2048; i += 256) {
        int rr = i >> 5, ep = (i & 31) * 2;
        float u0 = sU[rr * 65 + ep], u1 = sU[rr * 65 + ep + 1];
        uint32_t h = bf16x2_of(u0, u1);
        float h0 = __uint_as_float(h << 16);
        float h1 = __uint_as_float(h & 0xFFFF0000u);
        uint32_t l = bf16x2_of(u0 - h0, u1 - h1);
        int gi = (r0 + rr) * 64 + ep;
        *(uint32_t*)((bf16*)g_Uh + gi) = h;
        *(uint32_t*)((bf16*)g_Ul + gi) = l;
    }
    for (int t = tid; t < 4096; t += 256) {
        int c = t >> 5, ii = (t & 31) * 2;
        __half2 h2 = __floats2half2_rn(sT[c * 64 + ii], sT[c * 64 + ii + 1]);
        *(__half2*)((__half*)g_ET + (size_t)c * NT + r0 + ii) = h2;
    }
}

// ============================================================================
// chunk prefetch: V (128x64, 2 bf16 planes) + ET (128x128 fp16)
// ============================================================================
__device__ __forceinline__ void load_chunk(uint32_t sb, int k, int tid) {
    const int buf = k & 1;
    const int i0 = k * TI;
    const uint32_t vd = sb + O_V + buf * 36864;
    #pragma unroll
    for (int r = 0; r < 4; r++) {
        int id = r * 512 + tid;                      // 0..2047
        int pl = id >> 10, rem = id & 1023, row = rem >> 3, q = rem & 7;
        const bf16* src = (pl ? g_Vl : g_Vh) + (i0 + row) * 64 + q * 8;
        cpasync16(vd + pl * 18432 + row * (RS * 2) + q * 16, src);
    }
    const uint32_t ed = sb + O_E + buf * 34816;
    #pragma unroll
    for (int r = 0; r < 4; r++) {
        int id = r * 512 + tid;                      // 0..2047
        int row = id >> 4, q = id & 15;
        const __half* src = g_ET + (size_t)row * NT + i0 + q * 8;
        cpasync16(ed + row * (RSE * 2) + q * 16, src);
    }
}

// ============================================================================
// main: 128 CTAs x 64-j tile, 512 threads; GEMM1 bf16 3-pass -> sigmoid ->
//       GEMM2 fp16 1-pass, TI=128 per chunk
// ============================================================================
__global__ void __launch_bounds__(512, 1) main_kernel(const float* __restrict__ states,
                                                      const float* __restrict__ bptr,
                                                      float* __restrict__ out) {
    extern __shared__ char smem[];
    const uint32_t sb = s2u(smem);
    const int tid = threadIdx.x, w = tid >> 5, lane = tid & 31;
    const int jb = blockIdx.x * 64;
    const float bias = __ldg(bptr);

    const int lm = lane >> 3, lr = lane & 7;
    const int aRow = lr + (lm & 1) * 8;
    const int aCol = (lm >> 1) * 8;
    const int bRow = lr + (lm >> 1) * 8;
    const int bCol = (lm & 1) * 8;

    const int i0w = (w >> 1) * 16;     // GEMM1: 16i x 32j per warp (8 x 2 grid)
    const int jn0 = (w & 1) * 32;
    const int j0w = (w >> 2) * 16;     // GEMM2: 16j x 32c per warp (4 x 4 grid)
    const int c0w = (w & 3) * 32;

    // ---- persistent U tile + chunk 0 ----
    #pragma unroll
    for (int r = 0; r < 2; r++) {
        int id = r * 512 + tid;                      // 0..1023
        int pl = id >> 9, rem = id & 511, row = rem >> 3, q = rem & 7;
        const bf16* src = (pl ? g_Ul : g_Uh) + (jb + row) * 64 + q * 8;
        cpasync16(sb + (pl ? O_UL : O_UH) + row * (RS * 2) + q * 16, src);
    }
    load_chunk(sb, 0, tid);
    CP_COMMIT();
    CP_WAIT0();
    __syncthreads();

    float cacc[4][4];
    #pragma unroll
    for (int q = 0; q < 4; q++)
        #pragma unroll
        for (int v = 0; v < 4; v++) cacc[q][v] = 0.0f;

    for (int k = 0; k < NCH; k++) {
        const int buf = k & 1;
        if (k + 1 < NCH) load_chunk(sb, k + 1, tid);
        CP_COMMIT();

        // ---- GEMM1: S[16i x 32j] = V . U^T  (VhUh, VlUh, VhUl) ----
        const uint32_t vbase = sb + O_V + buf * 36864;
        uint32_t VhF[4][4], VlF[4][4];
        #pragma unroll
        for (int kk = 0; kk < 4; kk++)
            ldsm4(VhF[kk], vbase + ((i0w + aRow) * RS + kk * 16 + aCol) * 2);
        #pragma unroll
        for (int kk = 0; kk < 4; kk++)
            ldsm4(VlF[kk], vbase + 18432 + ((i0w + aRow) * RS + kk * 16 + aCol) * 2);

        float sacc[4][4];
        #pragma unroll
        for (int q = 0; q < 4; q++)
            #pragma unroll
            for (int v = 0; v < 4; v++) sacc[q][v] = 0.0f;

        #pragma unroll
        for (int kk = 0; kk < 4; kk++) {
            uint32_t uh0[4], uh1[4];
            ldsm4(uh0, sb + O_UH + ((jn0 + bRow) * RS + kk * 16 + bCol) * 2);
            ldsm4(uh1, sb + O_UH + ((jn0 + 16 + bRow) * RS + kk * 16 + bCol) * 2);
            mma_bf(sacc[0], VhF[kk], uh0); mma_bf(sacc[1], VhF[kk], uh0 + 2);
            mma_bf(sacc[2], VhF[kk], uh1); mma_bf(sacc[3], VhF[kk], uh1 + 2);
            mma_bf(sacc[0], VlF[kk], uh0); mma_bf(sacc[1], VlF[kk], uh0 + 2);
            mma_bf(sacc[2], VlF[kk], uh1); mma_bf(sacc[3], VlF[kk], uh1 + 2);
            uint32_t ul0[4], ul1[4];
            ldsm4(ul0, sb + O_UL + ((jn0 + bRow) * RS + kk * 16 + bCol) * 2);
            ldsm4(ul1, sb + O_UL + ((jn0 + 16 + bRow) * RS + kk * 16 + bCol) * 2);
            mma_bf(sacc[0], VhF[kk], ul0); mma_bf(sacc[1], VhF[kk], ul0 + 2);
            mma_bf(sacc[2], VhF[kk], ul1); mma_bf(sacc[3], VhF[kk], ul1 + 2);
        }

        // ---- sigmoid -> P fp16 ----
        {
            const int pr = i0w + (lane >> 2);
            const int pc = jn0 + (lane & 3) * 2;
            #pragma unroll
            for (int nt = 0; nt < 4; nt++) {
                float s0 = sigm(sacc[nt][0] + bias);
                float s1 = sigm(sacc[nt][1] + bias);
                float s2 = sigm(sacc[nt][2] + bias);
                float s3 = sigm(sacc[nt][3] + bias);
                char* ph = smem + O_P + (pr * RS + pc + nt * 8) * 2;
                *(uint32_t*)ph = f16x2_of(s0, s1);
                *(uint32_t*)(ph + 8 * RS * 2) = f16x2_of(s2, s3);
            }
        }
        __syncthreads();

        // ---- GEMM2: C[16j x 32c] += P^T . ET  (fp16, K=128) ----
        {
            const uint32_t ebase = sb + O_E + buf * 34816;
            #pragma unroll
            for (int kk = 0; kk < 8; kk++) {
                uint32_t a[4];
                ldsm4t(a, sb + O_P + ((kk * 16 + bRow) * RS + j0w + bCol) * 2);
                #pragma unroll
                for (int ct = 0; ct < 2; ct++) {
                    uint32_t b[4];
                    ldsm4(b, ebase + ((c0w + ct * 16 + bRow) * RSE + kk * 16 + bCol) * 2);
                    mma_f16(cacc[ct * 2],     a, b);
                    mma_f16(cacc[ct * 2 + 1], a, b + 2);
                }
            }
        }

        CP_WAIT0();
        __syncthreads();
    }

    // ---- epilogue: out = states + C - diag*eff ----
    {
        const int jrb = jb + j0w + (lane >> 2);
        const int ccb = (lane & 3) * 2;
        #pragma unroll
        for (int h = 0; h < 2; h++) {
            const int j = jrb + h * 8;
            const float dg = g_diag[j];
            #pragma unroll
            for (int q = 0; q < 4; q++) {
                const int c = c0w + q * 8 + ccb;
                const int b = c >> 6, d = c & 63;
                const int idx = (b * NT + j) * 64 + d;
                float2 st = *(const float2*)&states[idx];
                float2 ef = *(const float2*)&g_eff[j * 128 + c];
                float2 o;
                o.x = st.x + cacc[q][h * 2]     - dg * ef.x;
                o.y = st.y + cacc[q][h * 2 + 1] - dg * ef.y;
                *(float2*)&out[idx] = o;
            }
        }
    }
}

// ============================================================================
extern "C" void kernel_launch(void* const* d_in, const int* in_sizes, int n_in,
                              void* d_out, int out_size) {
    const float* states = (const float*)d_in[0];  // [2,8192,64]
    const float* prof   = (const float*)d_in[1];  // [2,8192]
    const float* U      = (const float*)d_in[2];  // [8192,64]
    const float* W      = (const float*)d_in[3];  // [1,64,64]
    const float* bias   = (const float*)d_in[4];  // [1]
    float* out = (float*)d_out;

    cudaFuncSetAttribute(prep_kernel, cudaFuncAttributeMaxDynamicSharedMemorySize, PREP_SMEM);
    prep_kernel<<<NT / 64, 256, PREP_SMEM>>>(states, prof, U, W, bias);

    cudaFuncSetAttribute(main_kernel, cudaFuncAttributeMaxDynamicSharedMemorySize, SMEM_TOTAL);
    main_kernel<<<NT / 64, 512, SMEM_TOTAL>>>(states, bias, out);
}

// round 13
// speedup vs baseline: 11.9494x; 1.1848x over previous
#include <cuda_runtime.h>
#include <cuda_bf16.h>
#include <cuda_fp16.h>
#include <cstdint>

#define NT      8192
#define THRESH  0.7f
#define NCH     64          // i-chunks per CTA
#define TI      128         // i per chunk
#define RS      72          // V/U/P smem row stride in 16-bit elems (144 B)
#define RSE     136         // E smem row stride in 16-bit elems (272 B)

// ---------------- device scratch (__device__ globals; no allocs) ----------------
__device__ float  g_eff[NT * 128];        // gated states fp32 [task][c]
__device__ float  g_diag[NT];             // sigmoid(u_j . v_j + b)
__device__ __half g_Uh[NT * 64], g_Ul[NT * 64];   // U fp16 hi/lo split
__device__ __half g_Vf[NT * 64];                  // V fp16 (single plane)
__device__ __half g_ET[128 * NT];                 // Eff^T [c][i] fp16

// ---------------- helpers ----------------
__device__ __forceinline__ uint32_t s2u(const void* p) {
    uint32_t a;
    asm("{ .reg .u64 t; cvta.to.shared.u64 t, %1; cvt.u32.u64 %0, t; }" : "=r"(a) : "l"(p));
    return a;
}
__device__ __forceinline__ void cpasync16(uint32_t dst, const void* src) {
    asm volatile("cp.async.cg.shared.global [%0], [%1], 16;" :: "r"(dst), "l"(src));
}
#define CP_COMMIT() asm volatile("cp.async.commit_group;")
#define CP_WAIT0()  asm volatile("cp.async.wait_group 0;" ::: "memory")

__device__ __forceinline__ void ldsm4(uint32_t* r, uint32_t addr) {
    asm volatile("ldmatrix.sync.aligned.m8n8.x4.shared.b16 {%0,%1,%2,%3}, [%4];"
        : "=r"(r[0]), "=r"(r[1]), "=r"(r[2]), "=r"(r[3]) : "r"(addr));
}
__device__ __forceinline__ void ldsm4t(uint32_t* r, uint32_t addr) {
    asm volatile("ldmatrix.sync.aligned.m8n8.x4.trans.shared.b16 {%0,%1,%2,%3}, [%4];"
        : "=r"(r[0]), "=r"(r[1]), "=r"(r[2]), "=r"(r[3]) : "r"(addr));
}
__device__ __forceinline__ void mma_f16(float* c, const uint32_t* a, const uint32_t* b) {
    asm volatile("mma.sync.aligned.m16n8k16.row.col.f32.f16.f16.f32 "
        "{%0,%1,%2,%3}, {%4,%5,%6,%7}, {%8,%9}, {%0,%1,%2,%3};"
        : "+f"(c[0]), "+f"(c[1]), "+f"(c[2]), "+f"(c[3])
        : "r"(a[0]), "r"(a[1]), "r"(a[2]), "r"(a[3]), "r"(b[0]), "r"(b[1]));
}
__device__ __forceinline__ uint32_t f16x2_of(float lo, float hi) {
    uint32_t r; asm("cvt.rn.f16x2.f32 %0, %1, %2;" : "=r"(r) : "f"(hi), "f"(lo)); return r;
}
// sigmoid(x) = 0.5 + 0.5*tanh(x/2)  — single HW MUFU op
__device__ __forceinline__ float sigm(float x) {
    float t; asm("tanh.approx.f32 %0, %1;" : "=f"(t) : "f"(0.5f * x));
    return fmaf(0.5f, t, 0.5f);
}

// ---------------- SMEM layout (bytes) ----------------
#define O_UH 0                    // 64 x 144
#define O_UL 9216
#define O_V  18432                // + buf*18432        (2 bufs, 128 rows x 144B, fp16)
#define O_E  55296                // + buf*34816        (2 bufs, 128 rows x 272B)
#define O_P  124928               // 128 rows x 144B
#define SMEM_TOTAL 143360

// ============================================================================
// prep: per 64-row block — V=U@W (fp32) -> fp16, U fp16 hi/lo, diag, eff, ET
// ============================================================================
#define PREP_SMEM ((4096 + 64*65 + 128*64) * 4)
__global__ void __launch_bounds__(256) prep_kernel(const float* __restrict__ states,
                                                   const float* __restrict__ prof,
                                                   const float* __restrict__ U,
                                                   const float* __restrict__ W,
                                                   const float* __restrict__ bptr) {
    extern __shared__ float sm[];
    float* sW = sm;                    // [64][64]
    float* sU = sm + 4096;             // [64][65]
    float* sT = sm + 4096 + 64 * 65;   // [128 c][64 ii]
    const int tid = threadIdx.x;
    const int r0 = blockIdx.x * 64;
    const float bias = __ldg(bptr);

    for (int i = tid; i < 4096; i += 256) sW[i] = W[i];
    for (int i = tid; i < 4096; i += 256) {
        int r = i >> 6, e = i & 63;
        sU[r * 65 + e] = U[(r0 + r) * 64 + e];
    }
    for (int t = tid; t < 2048; t += 256) {
        int b = t >> 10, rem = t & 1023, ii = rem >> 4, d4 = rem & 15;
        int i = r0 + ii;
        float g = prof[b * NT + i] - THRESH;
        g = g > 0.0f ? g : 0.0f;
        float4 s4 = *(const float4*)&states[(b * NT + i) * 64 + d4 * 4];
        int c = b * 64 + d4 * 4;
        sT[(c + 0) * 64 + ii] = s4.x * g;
        sT[(c + 1) * 64 + ii] = s4.y * g;
        sT[(c + 2) * 64 + ii] = s4.z * g;
        sT[(c + 3) * 64 + ii] = s4.w * g;
        float4 e4; e4.x = s4.x * g; e4.y = s4.y * g; e4.z = s4.z * g; e4.w = s4.w * g;
        *(float4*)&g_eff[i * 128 + c] = e4;
    }
    __syncthreads();

    // V rows (fp32 accumulate), then fp16 store
    const int row = tid >> 2, f0 = (tid & 3) * 16;
    float acc[16];
    #pragma unroll
    for (int q = 0; q < 16; q++) acc[q] = 0.0f;
    #pragma unroll 8
    for (int e = 0; e < 64; e++) {
        float u = sU[row * 65 + e];
        #pragma unroll
        for (int q4 = 0; q4 < 4; q4++) {
            float4 wv = *(const float4*)&sW[e * 64 + f0 + q4 * 4];
            acc[q4 * 4 + 0] += u * wv.x; acc[q4 * 4 + 1] += u * wv.y;
            acc[q4 * 4 + 2] += u * wv.z; acc[q4 * 4 + 3] += u * wv.w;
        }
    }
    const int base = (r0 + row) * 64 + f0;
    #pragma unroll
    for (int q = 0; q < 16; q += 2)
        *(uint32_t*)((__half*)g_Vf + base + q) = f16x2_of(acc[q], acc[q + 1]);

    // diag: quad-reduce u.v (fp32 path)
    float s = 0.0f;
    #pragma unroll
    for (int q = 0; q < 16; q++) s += acc[q] * sU[row * 65 + f0 + q];
    s += __shfl_xor_sync(0xffffffffu, s, 1);
    s += __shfl_xor_sync(0xffffffffu, s, 2);
    if ((tid & 3) == 0) g_diag[r0 + row] = sigm(s + bias);

    // U fp16 hi/lo splits
    for (int i = tid; i < 2048; i += 256) {
        int rr = i >> 5, ep = (i & 31) * 2;
        float u0 = sU[rr * 65 + ep], u1 = sU[rr * 65 + ep + 1];
        __half a0 = __float2half_rn(u0), a1 = __float2half_rn(u1);
        float l0 = u0 - __half2float(a0), l1 = u1 - __half2float(a1);
        int gi = (r0 + rr) * 64 + ep;
        *(__half2*)((__half*)g_Uh + gi) = __halves2half2(a0, a1);
        *(__half2*)((__half*)g_Ul + gi) = __halves2half2(__float2half_rn(l0), __float2half_rn(l1));
    }
    // ET fp16
    for (int t = tid; t < 4096; t += 256) {
        int c = t >> 5, ii = (t & 31) * 2;
        __half2 h2 = __floats2half2_rn(sT[c * 64 + ii], sT[c * 64 + ii + 1]);
        *(__half2*)((__half*)g_ET + (size_t)c * NT + r0 + ii) = h2;
    }
}

// ============================================================================
// chunk prefetch: V (128x64 fp16, 1 plane) + ET (128x128 fp16)
// ============================================================================
__device__ __forceinline__ void load_chunk(uint32_t sb, int k, int tid) {
    const int buf = k & 1;
    const int i0 = k * TI;
    const uint32_t vd = sb + O_V + buf * 18432;
    #pragma unroll
    for (int r = 0; r < 2; r++) {
        int id = r * 512 + tid;                      // 0..1023
        int row = id >> 3, q = id & 7;
        const __half* src = g_Vf + (i0 + row) * 64 + q * 8;
        cpasync16(vd + row * (RS * 2) + q * 16, src);
    }
    const uint32_t ed = sb + O_E + buf * 34816;
    #pragma unroll
    for (int r = 0; r < 4; r++) {
        int id = r * 512 + tid;                      // 0..2047
        int row = id >> 4, q = id & 15;
        const __half* src = g_ET + (size_t)row * NT + i0 + q * 8;
        cpasync16(ed + row * (RSE * 2) + q * 16, src);
    }
}

// ============================================================================
// main: 128 CTAs x 64-j tile, 512 threads; GEMM1 fp16 2-pass (V, Uh+Ul) ->
//       sigmoid -> GEMM2 fp16 1-pass, TI=128 per chunk
// ============================================================================
__global__ void __launch_bounds__(512, 1) main_kernel(const float* __restrict__ states,
                                                      const float* __restrict__ bptr,
                                                      float* __restrict__ out) {
    extern __shared__ char smem[];
    const uint32_t sb = s2u(smem);
    const int tid = threadIdx.x, w = tid >> 5, lane = tid & 31;
    const int jb = blockIdx.x * 64;
    const float bias = __ldg(bptr);

    const int lm = lane >> 3, lr = lane & 7;
    const int aRow = lr + (lm & 1) * 8;
    const int aCol = (lm >> 1) * 8;
    const int bRow = lr + (lm >> 1) * 8;
    const int bCol = (lm & 1) * 8;

    const int i0w = (w >> 1) * 16;     // GEMM1: 16i x 32j per warp (8 x 2 grid)
    const int jn0 = (w & 1) * 32;
    const int j0w = (w >> 2) * 16;     // GEMM2: 16j x 32c per warp (4 x 4 grid)
    const int c0w = (w & 3) * 32;

    // ---- persistent U tile (2 fp16 planes) + chunk 0 ----
    #pragma unroll
    for (int r = 0; r < 2; r++) {
        int id = r * 512 + tid;                      // 0..1023
        int pl = id >> 9, rem = id & 511, row = rem >> 3, q = rem & 7;
        const __half* src = (pl ? g_Ul : g_Uh) + (jb + row) * 64 + q * 8;
        cpasync16(sb + (pl ? O_UL : O_UH) + row * (RS * 2) + q * 16, src);
    }
    load_chunk(sb, 0, tid);
    CP_COMMIT();
    CP_WAIT0();
    __syncthreads();

    float cacc[4][4];
    #pragma unroll
    for (int q = 0; q < 4; q++)
        #pragma unroll
        for (int v = 0; v < 4; v++) cacc[q][v] = 0.0f;

    for (int k = 0; k < NCH; k++) {
        const int buf = k & 1;
        if (k + 1 < NCH) load_chunk(sb, k + 1, tid);
        CP_COMMIT();

        // ---- GEMM1: S[16i x 32j] = V . U^T  (2 passes: V.Uh, V.Ul) ----
        const uint32_t vbase = sb + O_V + buf * 18432;
        uint32_t VF[4][4];
        #pragma unroll
        for (int kk = 0; kk < 4; kk++)
            ldsm4(VF[kk], vbase + ((i0w + aRow) * RS + kk * 16 + aCol) * 2);

        float sacc[4][4];
        #pragma unroll
        for (int q = 0; q < 4; q++)
            #pragma unroll
            for (int v = 0; v < 4; v++) sacc[q][v] = 0.0f;

        #pragma unroll
        for (int kk = 0; kk < 4; kk++) {
            uint32_t uh0[4], uh1[4];
            ldsm4(uh0, sb + O_UH + ((jn0 + bRow) * RS + kk * 16 + bCol) * 2);
            ldsm4(uh1, sb + O_UH + ((jn0 + 16 + bRow) * RS + kk * 16 + bCol) * 2);
            mma_f16(sacc[0], VF[kk], uh0); mma_f16(sacc[1], VF[kk], uh0 + 2);
            mma_f16(sacc[2], VF[kk], uh1); mma_f16(sacc[3], VF[kk], uh1 + 2);
            uint32_t ul0[4], ul1[4];
            ldsm4(ul0, sb + O_UL + ((jn0 + bRow) * RS + kk * 16 + bCol) * 2);
            ldsm4(ul1, sb + O_UL + ((jn0 + 16 + bRow) * RS + kk * 16 + bCol) * 2);
            mma_f16(sacc[0], VF[kk], ul0); mma_f16(sacc[1], VF[kk], ul0 + 2);
            mma_f16(sacc[2], VF[kk], ul1); mma_f16(sacc[3], VF[kk], ul1 + 2);
        }

        // ---- sigmoid -> P fp16 ----
        {
            const int pr = i0w + (lane >> 2);
            const int pc = jn0 + (lane & 3) * 2;
            #pragma unroll
            for (int nt = 0; nt < 4; nt++) {
                float s0 = sigm(sacc[nt][0] + bias);
                float s1 = sigm(sacc[nt][1] + bias);
                float s2 = sigm(sacc[nt][2] + bias);
                float s3 = sigm(sacc[nt][3] + bias);
                char* ph = smem + O_P + (pr * RS + pc + nt * 8) * 2;
                *(uint32_t*)ph = f16x2_of(s0, s1);
                *(uint32_t*)(ph + 8 * RS * 2) = f16x2_of(s2, s3);
            }
        }
        __syncthreads();

        // ---- GEMM2: C[16j x 32c] += P^T . ET  (fp16, K=128) ----
        {
            const uint32_t ebase = sb + O_E + buf * 34816;
            #pragma unroll
            for (int kk = 0; kk < 8; kk++) {
                uint32_t a[4];
                ldsm4t(a, sb + O_P + ((kk * 16 + bRow) * RS + j0w + bCol) * 2);
                #pragma unroll
                for (int ct = 0; ct < 2; ct++) {
                    uint32_t b[4];
                    ldsm4(b, ebase + ((c0w + ct * 16 + bRow) * RSE + kk * 16 + bCol) * 2);
                    mma_f16(cacc[ct * 2],     a, b);
                    mma_f16(cacc[ct * 2 + 1], a, b + 2);
                }
            }
        }

        CP_WAIT0();
        __syncthreads();
    }

    // ---- epilogue: out = states + C - diag*eff ----
    {
        const int jrb = jb + j0w + (lane >> 2);
        const int ccb = (lane & 3) * 2;
        #pragma unroll
        for (int h = 0; h < 2; h++) {
            const int j = jrb + h * 8;
            const float dg = g_diag[j];
            #pragma unroll
            for (int q = 0; q < 4; q++) {
                const int c = c0w + q * 8 + ccb;
                const int b = c >> 6, d = c & 63;
                const int idx = (b * NT + j) * 64 + d;
                float2 st = *(const float2*)&states[idx];
                float2 ef = *(const float2*)&g_eff[j * 128 + c];
                float2 o;
                o.x = st.x + cacc[q][h * 2]     - dg * ef.x;
                o.y = st.y + cacc[q][h * 2 + 1] - dg * ef.y;
                *(float2*)&out[idx] = o;
            }
        }
    }
}

// ============================================================================
extern "C" void kernel_launch(void* const* d_in, const int* in_sizes, int n_in,
                              void* d_out, int out_size) {
    const float* states = (const float*)d_in[0];  // [2,8192,64]
    const float* prof   = (const float*)d_in[1];  // [2,8192]
    const float* U      = (const float*)d_in[2];  // [8192,64]
    const float* W      = (const float*)d_in[3];  // [1,64,64]
    const float* bias   = (const float*)d_in[4];  // [1]
    float* out = (float*)d_out;

    cudaFuncSetAttribute(prep_kernel, cudaFuncAttributeMaxDynamicSharedMemorySize, PREP_SMEM);
    prep_kernel<<<NT / 64, 256, PREP_SMEM>>>(states, prof, U, W, bias);

    cudaFuncSetAttribute(main_kernel, cudaFuncAttributeMaxDynamicSharedMemorySize, SMEM_TOTAL);
    main_kernel<<<NT / 64, 512, SMEM_TOTAL>>>(states, bias, out);
}